// round 7
// baseline (speedup 1.0000x reference)
#include <cuda_runtime.h>
#include <cuda_bf16.h>
#include <cstdint>

// Sparsemax along last dim of a [ROWS, 32000] fp32 matrix.
//
// Exact, sort-free: tau solves sum_i max(x_i - tau, 0) = 1 and tau >= rowmax-1,
// so the support lies in C = {x > rowmax - 1} (~25 elems/row, Gaussian data).
//
// Persistent CTAs (grid = #SMs, 1024 threads). The row streams through TWO
// 64 KB SMEM half-buffers (independent mbarriers). After half A is copied to
// registers and barrier-released, the next row's half A TMA is issued while
// half B is still being copied — halving the per-row TMA idle window vs a
// single 128 KB buffer. 3 block barriers per row. All 32 warps redundantly
// run Michelot on the compacted candidate list (no broadcast barrier).

#define SMX_N        32000
#define SMX_HALF     16000          // floats per half
#define SMX_HALF4    4000           // float4 per half
#define SMX_HALFB    64000          // bytes per half
#define SMX_THREADS  1024
#define SMX_HVPT     4              // float4 per thread per half
#define SMX_NEG      (-3.0e38f)
#define SMX_CAP      1024

__device__ __forceinline__ uint32_t smx_smem_u32(const void* p) {
    uint32_t a;
    asm("{ .reg .u64 t; cvta.to.shared.u64 t, %1; cvt.u32.u64 %0, t; }"
        : "=r"(a) : "l"(p));
    return a;
}
__device__ __forceinline__ void smx_mbar_init(uint32_t mbar, uint32_t count) {
    asm volatile("mbarrier.init.shared.b64 [%0], %1;" :: "r"(mbar), "r"(count) : "memory");
}
__device__ __forceinline__ void smx_expect_tx(uint32_t mbar, uint32_t bytes) {
    asm volatile("mbarrier.arrive.expect_tx.shared.b64 _, [%0], %1;"
                 :: "r"(mbar), "r"(bytes) : "memory");
}
__device__ __forceinline__ void smx_bulk_g2s(uint32_t dst, const void* src,
                                             uint32_t bytes, uint32_t mbar) {
    asm volatile(
        "cp.async.bulk.shared::cta.global.mbarrier::complete_tx::bytes [%0], [%1], %2, [%3];"
        :: "r"(dst), "l"(src), "r"(bytes), "r"(mbar) : "memory");
}
__device__ __forceinline__ void smx_mbar_wait(uint32_t mbar, uint32_t parity) {
    asm volatile(
        "{\n\t"
        ".reg .pred P;\n\t"
        "SMXW%=:\n\t"
        "mbarrier.try_wait.parity.acquire.cta.shared::cta.b64 P, [%0], %1, 0x989680;\n\t"
        "@P bra SMXD%=;\n\t"
        "bra SMXW%=;\n\t"
        "SMXD%=:\n\t"
        "}"
        :: "r"(mbar), "r"(parity) : "memory");
}
__device__ __forceinline__ void smx_fence_async() {
    asm volatile("fence.proxy.async.shared::cta;" ::: "memory");
}

// order-preserving float<->uint for shared atomicMax
__device__ __forceinline__ unsigned smx_enc(float f) {
    unsigned b = __float_as_uint(f);
    return (b & 0x80000000u) ? ~b : (b | 0x80000000u);
}
__device__ __forceinline__ float smx_dec(unsigned u) {
    return (u & 0x80000000u) ? __uint_as_float(u & 0x7fffffffu)
                             : __uint_as_float(~u);
}

extern __shared__ float smx_buf[];   // 2 halves * 16000 floats = 128 KB

__global__ __launch_bounds__(SMX_THREADS, 1)
void sparsemax_kernel(const float* __restrict__ x, float* __restrict__ y, int rows) {
    const int t    = threadIdx.x;
    const int lane = t & 31;
    const int stride = gridDim.x;

    __shared__ __align__(8) uint64_t s_mbarA, s_mbarB;
    __shared__ unsigned s_maxbits[2];
    __shared__ int      s_cnt[2];
    __shared__ float    s_red[2][2];          // fallback accumulators
    __shared__ float    s_cand[2][SMX_CAP];

    const uint32_t mbarA = smx_smem_u32(&s_mbarA);
    const uint32_t mbarB = smx_smem_u32(&s_mbarB);
    const uint32_t sbufA = smx_smem_u32(smx_buf);
    const uint32_t sbufB = smx_smem_u32(smx_buf + SMX_HALF);

    if (t == 0) {
        smx_mbar_init(mbarA, 1);
        smx_mbar_init(mbarB, 1);
        s_maxbits[0] = 0u;  s_cnt[0] = 0;
        s_maxbits[1] = 0u;  s_cnt[1] = 0;
    }
    __syncthreads();

    const int row0 = blockIdx.x;
    if (row0 >= rows) return;

    if (t == 0) {
        const float* rp = x + (size_t)row0 * SMX_N;
        smx_expect_tx(mbarA, SMX_HALFB);
        smx_bulk_g2s(sbufA, rp, SMX_HALFB, mbarA);
        smx_expect_tx(mbarB, SMX_HALFB);
        smx_bulk_g2s(sbufB, rp + SMX_HALF, SMX_HALFB, mbarB);
    }

    uint32_t parity = 0;   // both mbars flip once per row
    unsigned p = 0;        // row-parity for scratch slots

    for (int r = row0; r < rows; r += stride) {
        const float* nxt = x + (size_t)(r + stride) * SMX_N;
        const bool have_next = (r + stride < rows);

        // ---- half A: copy to regs with fused max ----
        smx_mbar_wait(mbarA, parity);
        float4 vA[SMX_HVPT];
        float m = SMX_NEG;
        {
            const float4* s4 = reinterpret_cast<const float4*>(smx_buf);
            #pragma unroll
            for (int i = 0; i < SMX_HVPT; i++) {
                const int idx = i * SMX_THREADS + t;
                if (idx < SMX_HALF4) {
                    vA[i] = s4[idx];
                    m = fmaxf(m, fmaxf(fmaxf(vA[i].x, vA[i].y), fmaxf(vA[i].z, vA[i].w)));
                } else {
                    vA[i] = make_float4(SMX_NEG, SMX_NEG, SMX_NEG, SMX_NEG);
                }
            }
        }
        __syncthreads();   // barrier 1: half A reads done
        if (t == 0 && have_next) {
            smx_fence_async();
            smx_expect_tx(mbarA, SMX_HALFB);
            smx_bulk_g2s(sbufA, nxt, SMX_HALFB, mbarA);
        }

        // ---- half B: copy to regs with fused max ----
        smx_mbar_wait(mbarB, parity);
        float4 vB[SMX_HVPT];
        {
            const float4* s4 = reinterpret_cast<const float4*>(smx_buf + SMX_HALF);
            #pragma unroll
            for (int i = 0; i < SMX_HVPT; i++) {
                const int idx = i * SMX_THREADS + t;
                if (idx < SMX_HALF4) {
                    vB[i] = s4[idx];
                    m = fmaxf(m, fmaxf(fmaxf(vB[i].x, vB[i].y), fmaxf(vB[i].z, vB[i].w)));
                } else {
                    vB[i] = make_float4(SMX_NEG, SMX_NEG, SMX_NEG, SMX_NEG);
                }
            }
        }
        // warp max-reduce + shared atomicMax (pre-barrier)
        #pragma unroll
        for (int o = 16; o; o >>= 1)
            m = fmaxf(m, __shfl_xor_sync(0xffffffffu, m, o));
        if (lane == 0) atomicMax(&s_maxbits[p], smx_enc(m));

        __syncthreads();   // barrier 2: half B reads done + rowmax published
        if (t == 0 && have_next) {
            smx_fence_async();
            smx_expect_tx(mbarB, SMX_HALFB);
            smx_bulk_g2s(sbufB, nxt + SMX_HALF, SMX_HALFB, mbarB);
        }

        const float thr = smx_dec(s_maxbits[p]) - 1.0f;   // tau >= thr always
        if (t == 1) { s_maxbits[p ^ 1] = 0u; s_cnt[p ^ 1] = 0; }

        // ---- compact candidates {x > thr} ----
        #pragma unroll
        for (int i = 0; i < SMX_HVPT; i++) {
            const float a0 = vA[i].x, a1 = vA[i].y, a2 = vA[i].z, a3 = vA[i].w;
            if (a0 > thr) { int k = atomicAdd(&s_cnt[p], 1); if (k < SMX_CAP) s_cand[p][k] = a0; }
            if (a1 > thr) { int k = atomicAdd(&s_cnt[p], 1); if (k < SMX_CAP) s_cand[p][k] = a1; }
            if (a2 > thr) { int k = atomicAdd(&s_cnt[p], 1); if (k < SMX_CAP) s_cand[p][k] = a2; }
            if (a3 > thr) { int k = atomicAdd(&s_cnt[p], 1); if (k < SMX_CAP) s_cand[p][k] = a3; }
        }
        #pragma unroll
        for (int i = 0; i < SMX_HVPT; i++) {
            const float a0 = vB[i].x, a1 = vB[i].y, a2 = vB[i].z, a3 = vB[i].w;
            if (a0 > thr) { int k = atomicAdd(&s_cnt[p], 1); if (k < SMX_CAP) s_cand[p][k] = a0; }
            if (a1 > thr) { int k = atomicAdd(&s_cnt[p], 1); if (k < SMX_CAP) s_cand[p][k] = a1; }
            if (a2 > thr) { int k = atomicAdd(&s_cnt[p], 1); if (k < SMX_CAP) s_cand[p][k] = a2; }
            if (a3 > thr) { int k = atomicAdd(&s_cnt[p], 1); if (k < SMX_CAP) s_cand[p][k] = a3; }
        }
        __syncthreads();   // barrier 3: candidate list complete
        const int cnt = s_cnt[p];

        float tau;
        if (cnt <= SMX_CAP) {
            // ---- every warp redundantly: Michelot on the candidate list ----
            tau = thr;
            float prevc = -1.0f;
            #pragma unroll 1
            for (int it = 0; it < 64; it++) {
                float s = 0.0f, c = 0.0f;
                for (int j = lane; j < cnt; j += 32) {
                    const float z = s_cand[p][j];
                    if (z > tau) { s += z; c += 1.0f; }
                }
                #pragma unroll
                for (int o = 16; o; o >>= 1) {
                    s += __shfl_xor_sync(0xffffffffu, s, o);
                    c += __shfl_xor_sync(0xffffffffu, c, o);
                }
                tau = (s - 1.0f) / c;
                if (c == prevc) break;        // fixed point: exact tau
                prevc = c;
            }
        } else {
            // ---- fallback: full-row Michelot via shared atomics (rare) ----
            if (t == 0) { s_red[0][0] = 0.f; s_red[0][1] = 0.f;
                          s_red[1][0] = 0.f; s_red[1][1] = 0.f; }
            __syncthreads();
            tau = thr;
            float prevc = -1.0f;
            unsigned q = 0;
            #pragma unroll 1
            for (int it = 0; it < 64; it++) {
                float s = 0.0f, c = 0.0f;
                #pragma unroll
                for (int i = 0; i < SMX_HVPT; i++) {
                    if (vA[i].x > tau) { s += vA[i].x; c += 1.0f; }
                    if (vA[i].y > tau) { s += vA[i].y; c += 1.0f; }
                    if (vA[i].z > tau) { s += vA[i].z; c += 1.0f; }
                    if (vA[i].w > tau) { s += vA[i].w; c += 1.0f; }
                    if (vB[i].x > tau) { s += vB[i].x; c += 1.0f; }
                    if (vB[i].y > tau) { s += vB[i].y; c += 1.0f; }
                    if (vB[i].z > tau) { s += vB[i].z; c += 1.0f; }
                    if (vB[i].w > tau) { s += vB[i].w; c += 1.0f; }
                }
                #pragma unroll
                for (int o = 16; o; o >>= 1) {
                    s += __shfl_xor_sync(0xffffffffu, s, o);
                    c += __shfl_xor_sync(0xffffffffu, c, o);
                }
                if (lane == 0) { atomicAdd(&s_red[q][0], s); atomicAdd(&s_red[q][1], c); }
                if (t == 0)    { s_red[q ^ 1][0] = 0.f; s_red[q ^ 1][1] = 0.f; }
                __syncthreads();
                const float S = s_red[q][0], C = s_red[q][1];
                __syncthreads();
                tau = (S - 1.0f) / C;
                if (C == prevc) break;
                prevc = C;
                q ^= 1;
            }
        }

        // ---- output: max(x - tau, 0), coalesced, evict-first ----
        float4* __restrict__ yr = reinterpret_cast<float4*>(y + (size_t)r * SMX_N);
        #pragma unroll
        for (int i = 0; i < SMX_HVPT; i++) {
            const int idx = i * SMX_THREADS + t;
            if (idx < SMX_HALF4) {
                float4 o;
                o.x = fmaxf(vA[i].x - tau, 0.0f);
                o.y = fmaxf(vA[i].y - tau, 0.0f);
                o.z = fmaxf(vA[i].z - tau, 0.0f);
                o.w = fmaxf(vA[i].w - tau, 0.0f);
                __stcs(&yr[idx], o);
            }
        }
        #pragma unroll
        for (int i = 0; i < SMX_HVPT; i++) {
            const int idx = i * SMX_THREADS + t;
            if (idx < SMX_HALF4) {
                float4 o;
                o.x = fmaxf(vB[i].x - tau, 0.0f);
                o.y = fmaxf(vB[i].y - tau, 0.0f);
                o.z = fmaxf(vB[i].z - tau, 0.0f);
                o.w = fmaxf(vB[i].w - tau, 0.0f);
                __stcs(&yr[SMX_HALF4 + idx], o);
            }
        }

        parity ^= 1u;
        p ^= 1u;
    }
}

extern "C" void kernel_launch(void* const* d_in, const int* in_sizes, int n_in,
                              void* d_out, int out_size) {
    const float* x = (const float*)d_in[0];
    float* y = (float*)d_out;
    const int rows = in_sizes[0] / SMX_N;

    int dev = 0, sms = 148;
    cudaGetDevice(&dev);
    cudaDeviceGetAttribute(&sms, cudaDevAttrMultiProcessorCount, dev);

    static bool attr_done = false;
    if (!attr_done) {
        cudaFuncSetAttribute(sparsemax_kernel,
                             cudaFuncAttributeMaxDynamicSharedMemorySize,
                             2 * SMX_HALFB);
        attr_done = true;
    }

    int grid = rows < sms ? rows : sms;
    sparsemax_kernel<<<grid, SMX_THREADS, 2 * SMX_HALFB>>>(x, y, rows);
}

// round 8
// speedup vs baseline: 1.5055x; 1.5055x over previous
#include <cuda_runtime.h>
#include <cuda_bf16.h>
#include <cstdint>

// Sparsemax along last dim of a [ROWS, 32000] fp32 matrix.
//
// Exact, sort-free: tau solves sum_i max(x_i - tau, 0) = 1 and tau >= rowmax-1,
// so the support lies in C = {x > rowmax - 1} (~25 elems/row, Gaussian data).
//
// Persistent CTAs (grid = #SMs, 1024 threads). Whole row TMA'd into a single
// 128 KB SMEM buffer one row ahead; row register-resident (8 x float4/thread).
// NEW vs best: cp.async.bulk.prefetch.L2 pulls the row TWO ahead into L2
// during the copy window (no SMEM traffic -> no crossbar contention), so the
// DRAM read stream stays continuous; the g2s TMA then mostly hits L2.
// Two block barriers per row; all warps redundantly run Michelot on the
// compacted candidate list (no broadcast barrier).

#define SMX_N        32000
#define SMX_N4       8000
#define SMX_ROWBYTES 128000
#define SMX_THREADS  1024
#define SMX_VPT      8
#define SMX_NEG      (-3.0e38f)
#define SMX_CAP      1024

__device__ __forceinline__ uint32_t smx_smem_u32(const void* p) {
    uint32_t a;
    asm("{ .reg .u64 t; cvta.to.shared.u64 t, %1; cvt.u32.u64 %0, t; }"
        : "=r"(a) : "l"(p));
    return a;
}
__device__ __forceinline__ void smx_mbar_init(uint32_t mbar, uint32_t count) {
    asm volatile("mbarrier.init.shared.b64 [%0], %1;" :: "r"(mbar), "r"(count) : "memory");
}
__device__ __forceinline__ void smx_expect_tx(uint32_t mbar, uint32_t bytes) {
    asm volatile("mbarrier.arrive.expect_tx.shared.b64 _, [%0], %1;"
                 :: "r"(mbar), "r"(bytes) : "memory");
}
__device__ __forceinline__ void smx_bulk_g2s(uint32_t dst, const void* src,
                                             uint32_t bytes, uint32_t mbar) {
    asm volatile(
        "cp.async.bulk.shared::cta.global.mbarrier::complete_tx::bytes [%0], [%1], %2, [%3];"
        :: "r"(dst), "l"(src), "r"(bytes), "r"(mbar) : "memory");
}
__device__ __forceinline__ void smx_l2_prefetch(const void* src, uint32_t bytes) {
    asm volatile("cp.async.bulk.prefetch.L2.global [%0], %1;"
                 :: "l"(src), "r"(bytes) : "memory");
}
__device__ __forceinline__ void smx_mbar_wait(uint32_t mbar, uint32_t parity) {
    asm volatile(
        "{\n\t"
        ".reg .pred P;\n\t"
        "SMXW%=:\n\t"
        "mbarrier.try_wait.parity.acquire.cta.shared::cta.b64 P, [%0], %1, 0x989680;\n\t"
        "@P bra SMXD%=;\n\t"
        "bra SMXW%=;\n\t"
        "SMXD%=:\n\t"
        "}"
        :: "r"(mbar), "r"(parity) : "memory");
}
__device__ __forceinline__ void smx_fence_async() {
    asm volatile("fence.proxy.async.shared::cta;" ::: "memory");
}

// order-preserving float<->uint for shared atomicMax
__device__ __forceinline__ unsigned smx_enc(float f) {
    unsigned b = __float_as_uint(f);
    return (b & 0x80000000u) ? ~b : (b | 0x80000000u);
}
__device__ __forceinline__ float smx_dec(unsigned u) {
    return (u & 0x80000000u) ? __uint_as_float(u & 0x7fffffffu)
                             : __uint_as_float(~u);
}

extern __shared__ float smx_buf[];   // 32000 floats = 128 KB

__global__ __launch_bounds__(SMX_THREADS, 1)
void sparsemax_kernel(const float* __restrict__ x, float* __restrict__ y, int rows) {
    const int t    = threadIdx.x;
    const int lane = t & 31;
    const int stride = gridDim.x;

    __shared__ __align__(8) uint64_t s_mbar;
    __shared__ unsigned s_maxbits[2];
    __shared__ int      s_cnt[2];
    __shared__ float    s_red[2][2];          // fallback accumulators
    __shared__ float    s_cand[2][SMX_CAP];

    const uint32_t mbar = smx_smem_u32(&s_mbar);
    const uint32_t sbuf = smx_smem_u32(smx_buf);

    if (t == 0) {
        smx_mbar_init(mbar, 1);
        s_maxbits[0] = 0u;  s_cnt[0] = 0;
        s_maxbits[1] = 0u;  s_cnt[1] = 0;
    }
    __syncthreads();

    const int row0 = blockIdx.x;
    if (row0 >= rows) return;

    if (t == 0) {
        smx_expect_tx(mbar, SMX_ROWBYTES);
        smx_bulk_g2s(sbuf, x + (size_t)row0 * SMX_N, SMX_ROWBYTES, mbar);
        // warm L2 one row further ahead
        if (row0 + stride < rows)
            smx_l2_prefetch(x + (size_t)(row0 + stride) * SMX_N, SMX_ROWBYTES);
    }

    uint32_t parity = 0;   // mbarrier phase
    unsigned p = 0;        // row-parity for scratch slots

    for (int r = row0; r < rows; r += stride) {
        smx_mbar_wait(mbar, parity);
        parity ^= 1u;

        // L2 prefetch for the row TWO ahead: DRAM->L2 only, no SMEM writes,
        // so it streams during the copy below without crossbar contention.
        if (t == 32 && r + 2 * stride < rows)
            smx_l2_prefetch(x + (size_t)(r + 2 * stride) * SMX_N, SMX_ROWBYTES);

        // ---- SMEM -> registers with fused running max ----
        float4 v[SMX_VPT];
        float m = SMX_NEG;
        const float4* s4 = reinterpret_cast<const float4*>(smx_buf);
        #pragma unroll
        for (int i = 0; i < SMX_VPT; i++) {
            const int idx = i * SMX_THREADS + t;
            if (idx < SMX_N4) {
                v[i] = s4[idx];
                m = fmaxf(m, fmaxf(fmaxf(v[i].x, v[i].y), fmaxf(v[i].z, v[i].w)));
            } else {
                v[i] = make_float4(SMX_NEG, SMX_NEG, SMX_NEG, SMX_NEG);
            }
        }

        // warp max-reduce + shared atomicMax (pre-barrier)
        #pragma unroll
        for (int o = 16; o; o >>= 1)
            m = fmaxf(m, __shfl_xor_sync(0xffffffffu, m, o));
        if (lane == 0) atomicMax(&s_maxbits[p], smx_enc(m));

        __syncthreads();   // barrier A: buffer reads done + rowmax published

        // t0: release buffer to the async proxy, g2s the next row (L2-hot)
        if (t == 0 && r + stride < rows) {
            smx_fence_async();
            smx_expect_tx(mbar, SMX_ROWBYTES);
            smx_bulk_g2s(sbuf, x + (size_t)(r + stride) * SMX_N, SMX_ROWBYTES, mbar);
        }

        const float thr = smx_dec(s_maxbits[p]) - 1.0f;   // tau >= thr always
        if (t == 1) { s_maxbits[p ^ 1] = 0u; s_cnt[p ^ 1] = 0; }  // prep next slot

        // ---- compact candidates {x > thr} into s_cand[p] ----
        #pragma unroll
        for (int i = 0; i < SMX_VPT; i++) {
            const float a0 = v[i].x, a1 = v[i].y, a2 = v[i].z, a3 = v[i].w;
            if (a0 > thr) { int k = atomicAdd(&s_cnt[p], 1); if (k < SMX_CAP) s_cand[p][k] = a0; }
            if (a1 > thr) { int k = atomicAdd(&s_cnt[p], 1); if (k < SMX_CAP) s_cand[p][k] = a1; }
            if (a2 > thr) { int k = atomicAdd(&s_cnt[p], 1); if (k < SMX_CAP) s_cand[p][k] = a2; }
            if (a3 > thr) { int k = atomicAdd(&s_cnt[p], 1); if (k < SMX_CAP) s_cand[p][k] = a3; }
        }
        __syncthreads();   // barrier B: candidate list complete
        const int cnt = s_cnt[p];

        float tau;
        if (cnt <= SMX_CAP) {
            // ---- every warp redundantly: Michelot on the candidate list ----
            tau = thr;
            float prevc = -1.0f;
            #pragma unroll 1
            for (int it = 0; it < 64; it++) {
                float s = 0.0f, c = 0.0f;
                for (int j = lane; j < cnt; j += 32) {
                    const float z = s_cand[p][j];
                    if (z > tau) { s += z; c += 1.0f; }
                }
                #pragma unroll
                for (int o = 16; o; o >>= 1) {
                    s += __shfl_xor_sync(0xffffffffu, s, o);
                    c += __shfl_xor_sync(0xffffffffu, c, o);
                }
                tau = (s - 1.0f) / c;
                if (c == prevc) break;        // fixed point: exact tau
                prevc = c;
            }
        } else {
            // ---- fallback: full-row Michelot via shared atomics (rare) ----
            if (t == 0) { s_red[0][0] = 0.f; s_red[0][1] = 0.f;
                          s_red[1][0] = 0.f; s_red[1][1] = 0.f; }
            __syncthreads();
            tau = thr;
            float prevc = -1.0f;
            unsigned q = 0;
            #pragma unroll 1
            for (int it = 0; it < 64; it++) {
                float s = 0.0f, c = 0.0f;
                #pragma unroll
                for (int i = 0; i < SMX_VPT; i++) {
                    if (v[i].x > tau) { s += v[i].x; c += 1.0f; }
                    if (v[i].y > tau) { s += v[i].y; c += 1.0f; }
                    if (v[i].z > tau) { s += v[i].z; c += 1.0f; }
                    if (v[i].w > tau) { s += v[i].w; c += 1.0f; }
                }
                #pragma unroll
                for (int o = 16; o; o >>= 1) {
                    s += __shfl_xor_sync(0xffffffffu, s, o);
                    c += __shfl_xor_sync(0xffffffffu, c, o);
                }
                if (lane == 0) { atomicAdd(&s_red[q][0], s); atomicAdd(&s_red[q][1], c); }
                if (t == 0)    { s_red[q ^ 1][0] = 0.f; s_red[q ^ 1][1] = 0.f; }
                __syncthreads();
                const float S = s_red[q][0], C = s_red[q][1];
                __syncthreads();
                tau = (S - 1.0f) / C;
                if (C == prevc) break;
                prevc = C;
                q ^= 1;
            }
        }

        // ---- output: max(x - tau, 0), coalesced, evict-first ----
        float4* __restrict__ yr = reinterpret_cast<float4*>(y + (size_t)r * SMX_N);
        #pragma unroll
        for (int i = 0; i < SMX_VPT; i++) {
            const int idx = i * SMX_THREADS + t;
            if (idx < SMX_N4) {
                float4 o;
                o.x = fmaxf(v[i].x - tau, 0.0f);
                o.y = fmaxf(v[i].y - tau, 0.0f);
                o.z = fmaxf(v[i].z - tau, 0.0f);
                o.w = fmaxf(v[i].w - tau, 0.0f);
                __stcs(&yr[idx], o);
            }
        }

        p ^= 1u;
    }
}

extern "C" void kernel_launch(void* const* d_in, const int* in_sizes, int n_in,
                              void* d_out, int out_size) {
    const float* x = (const float*)d_in[0];
    float* y = (float*)d_out;
    const int rows = in_sizes[0] / SMX_N;

    int dev = 0, sms = 148;
    cudaGetDevice(&dev);
    cudaDeviceGetAttribute(&sms, cudaDevAttrMultiProcessorCount, dev);

    static bool attr_done = false;
    if (!attr_done) {
        cudaFuncSetAttribute(sparsemax_kernel,
                             cudaFuncAttributeMaxDynamicSharedMemorySize,
                             SMX_ROWBYTES);
        attr_done = true;
    }

    int grid = rows < sms ? rows : sms;
    sparsemax_kernel<<<grid, SMX_THREADS, SMX_ROWBYTES>>>(x, y, rows);
}